// round 1
// baseline (speedup 1.0000x reference)
#include <cuda_runtime.h>
#include <cstdint>
#include <cstddef>

#define B_  256
#define T_  2048
#define D_  128
#define H_  128
#define G4_ 512                 // 4*H
#define M_  (B_ * T_)           // 524288

// Scratch (device globals — no cudaMalloc allowed)
__device__ float g_xp[(size_t)M_ * G4_];   // x @ W_ih^T + b_ih + b_hh   (1 GiB)
__device__ float g_hs[(size_t)M_ * H_];    // h_states [B][T][H]         (256 MiB)

// ---------------------------------------------------------------------------
// Kernel 1: x_proj GEMM.  C[m][n] = sum_k x[m][k] * W_ih[n][k] + b_ih[n]+b_hh[n]
// Tiles: BM=64, BN=64, K=128 fully smem-resident. 4x4 microtile per thread.
// ---------------------------------------------------------------------------
__global__ __launch_bounds__(256) void xproj_kernel(
    const float* __restrict__ x, const float* __restrict__ Wih,
    const float* __restrict__ bih, const float* __restrict__ bhh)
{
    extern __shared__ float4 smem_xp[];
    float4* As = smem_xp;            // [64 rows][32 k4]  (row-major, plain)
    float4* Bs = smem_xp + 64 * 32;  // [64 n  ][32 k4]  XOR-swizzled on k4

    const int m0 = blockIdx.x * 64;
    const int n0 = blockIdx.y * 64;
    const int tid = threadIdx.x;

    const float4* x4 = reinterpret_cast<const float4*>(x);
    const float4* w4 = reinterpret_cast<const float4*>(Wih);

    #pragma unroll
    for (int r = 0; r < 8; r++) {
        int idx = tid + 256 * r;          // 0..2047
        int row = idx >> 5;
        int k4  = idx & 31;
        As[row * 32 + k4] = x4[(size_t)(m0 + row) * 32 + k4];
        Bs[row * 32 + (k4 ^ (row & 31))] = w4[(size_t)(n0 + row) * 32 + k4];
    }
    __syncthreads();

    const int tn = tid & 15;   // 16 n-groups
    const int tm = tid >> 4;   // 16 m-groups

    float acc[4][4];
    #pragma unroll
    for (int i = 0; i < 4; i++)
        #pragma unroll
        for (int j = 0; j < 4; j++) acc[i][j] = 0.0f;

    #pragma unroll 4
    for (int k4 = 0; k4 < 32; k4++) {
        float4 a[4], b[4];
        #pragma unroll
        for (int i = 0; i < 4; i++)
            a[i] = As[(tm * 4 + i) * 32 + k4];
        #pragma unroll
        for (int j = 0; j < 4; j++) {
            int n = tn * 4 + j;
            b[j] = Bs[n * 32 + (k4 ^ (n & 31))];
        }
        #pragma unroll
        for (int i = 0; i < 4; i++)
            #pragma unroll
            for (int j = 0; j < 4; j++) {
                acc[i][j] = fmaf(a[i].x, b[j].x, acc[i][j]);
                acc[i][j] = fmaf(a[i].y, b[j].y, acc[i][j]);
                acc[i][j] = fmaf(a[i].z, b[j].z, acc[i][j]);
                acc[i][j] = fmaf(a[i].w, b[j].w, acc[i][j]);
            }
    }

    float bias[4];
    #pragma unroll
    for (int j = 0; j < 4; j++) {
        int n = n0 + tn * 4 + j;
        bias[j] = bih[n] + bhh[n];
    }

    float4* out4 = reinterpret_cast<float4*>(g_xp);
    #pragma unroll
    for (int i = 0; i < 4; i++) {
        size_t m = (size_t)(m0 + tm * 4 + i);
        float4 o;
        o.x = acc[i][0] + bias[0];
        o.y = acc[i][1] + bias[1];
        o.z = acc[i][2] + bias[2];
        o.w = acc[i][3] + bias[3];
        out4[m * (G4_ / 4) + (n0 >> 2) + tn] = o;
    }
}

// ---------------------------------------------------------------------------
// Kernel 2: persistent LSTM scan. 128 CTAs, 2 batch rows each, 256 threads.
// W_hh gates i,f (rows 0..255)  -> registers (thread t owns gate-row t)
// W_hh gates g,o (rows 256..511)-> smem, layout [k4][row] (conflict-free)
// h (2x128) broadcast from smem. c lives in a register of the combining thread.
// ---------------------------------------------------------------------------
__device__ __forceinline__ float sigmoid_f(float v) {
    return __fdividef(1.0f, 1.0f + __expf(-v));
}
__device__ __forceinline__ float tanh_f(float v) {
    // tanh(x) = 1 - 2/(e^{2x}+1); safe for +/-inf exp
    return 1.0f - __fdividef(2.0f, __expf(2.0f * v) + 1.0f);
}

__global__ __launch_bounds__(256, 1) void lstm_kernel(const float* __restrict__ Whh)
{
    extern __shared__ float smem_l[];
    float*  sh_h = smem_l;                 // [2][128]    (1 KiB)
    float*  gbuf = smem_l + 256;           // [2][512]    (4 KiB)
    float4* Wgo  = reinterpret_cast<float4*>(smem_l + 256 + 1024); // [32][256] float4 (128 KiB)

    const int tid = threadIdx.x;
    const int b0  = blockIdx.x * 2;
    const float4* W4 = reinterpret_cast<const float4*>(Whh);

    // Register-resident W for gate-row `tid` (i for tid<128, f otherwise)
    float4 wr[32];
    #pragma unroll
    for (int k4 = 0; k4 < 32; k4++)
        wr[k4] = W4[(size_t)tid * 32 + k4];

    // smem-resident W for gate-rows 256..511, transposed to [k4][row]
    #pragma unroll
    for (int i = 0; i < 32; i++) {
        int idx = tid + 256 * i;           // 0..8191
        int k4  = idx >> 8;
        int r   = idx & 255;
        Wgo[k4 * 256 + r] = W4[(size_t)(256 + r) * 32 + k4];
    }

    sh_h[tid] = 0.0f;                       // h0 = 0 (covers 2*128)
    float c_reg = 0.0f;

    const int row = tid >> 7;               // which of my 2 batch rows I combine
    const int j   = tid & 127;               // hidden index I combine

    const float* my_xp = g_xp + ((size_t)(b0 + row) * T_) * G4_;
    float*       my_hs = g_hs + (size_t)(b0 + row) * T_ * H_;

    __syncthreads();

    const float4* h40 = reinterpret_cast<const float4*>(sh_h);
    const float4* h41 = reinterpret_cast<const float4*>(sh_h + 128);

    for (int t = 0; t < T_; t++) {
        // prefetch x_proj for my combine slot (latency hidden by phase A)
        const float* xpt = my_xp + (size_t)t * G4_;
        float xpi = __ldg(xpt + j);
        float xpf = __ldg(xpt + 128 + j);
        float xpg = __ldg(xpt + 256 + j);
        float xpo = __ldg(xpt + 384 + j);

        // -------- phase A: dot products --------
        float a0 = 0.f, a1 = 0.f, q0 = 0.f, q1 = 0.f;
        #pragma unroll
        for (int k4 = 0; k4 < 32; k4++) {
            float4 h0 = h40[k4];                 // broadcast
            float4 h1 = h41[k4];                 // broadcast
            float4 w  = wr[k4];                  // registers
            float4 wg = Wgo[k4 * 256 + tid];     // conflict-free stream
            a0 = fmaf(w.x,  h0.x, a0); a0 = fmaf(w.y,  h0.y, a0);
            a0 = fmaf(w.z,  h0.z, a0); a0 = fmaf(w.w,  h0.w, a0);
            a1 = fmaf(w.x,  h1.x, a1); a1 = fmaf(w.y,  h1.y, a1);
            a1 = fmaf(w.z,  h1.z, a1); a1 = fmaf(w.w,  h1.w, a1);
            q0 = fmaf(wg.x, h0.x, q0); q0 = fmaf(wg.y, h0.y, q0);
            q0 = fmaf(wg.z, h0.z, q0); q0 = fmaf(wg.w, h0.w, q0);
            q1 = fmaf(wg.x, h1.x, q1); q1 = fmaf(wg.y, h1.y, q1);
            q1 = fmaf(wg.z, h1.z, q1); q1 = fmaf(wg.w, h1.w, q1);
        }
        gbuf[tid]             = a0;   // gate-row tid,     row 0
        gbuf[512 + tid]       = a1;   // gate-row tid,     row 1
        gbuf[256 + tid]       = q0;   // gate-row 256+tid, row 0
        gbuf[512 + 256 + tid] = q1;   // gate-row 256+tid, row 1
        __syncthreads();

        // -------- phase B: LSTM cell update --------
        float gi = gbuf[row * 512 + j]       + xpi;
        float gf = gbuf[row * 512 + 128 + j] + xpf;
        float gg = gbuf[row * 512 + 256 + j] + xpg;
        float go = gbuf[row * 512 + 384 + j] + xpo;

        float si = sigmoid_f(gi);
        float sf = sigmoid_f(gf);
        float so = sigmoid_f(go);
        float tg = tanh_f(gg);

        c_reg = fmaf(sf, c_reg, si * tg);
        float hn = so * tanh_f(c_reg);

        sh_h[row * 128 + j]       = hn;
        my_hs[(size_t)t * H_ + j] = hn;
        __syncthreads();
    }
}

// ---------------------------------------------------------------------------
// Kernel 3: attention pooling. One CTA per batch row.
// ---------------------------------------------------------------------------
__global__ __launch_bounds__(256) void attn_kernel(float* __restrict__ out)
{
    __shared__ float s_sc[T_];
    __shared__ float red[8];
    __shared__ float red2[256];

    const int b    = blockIdx.x;
    const int tid  = threadIdx.x;
    const int lane = tid & 31;
    const int warp = tid >> 5;

    const float*  hs  = g_hs + (size_t)b * T_ * H_;
    const float4* hs4 = reinterpret_cast<const float4*>(hs);

    const float4 hl = hs4[(size_t)(T_ - 1) * 32 + lane];

    // scores + running max
    float lmax = -3.0e38f;
    for (int t = warp; t < T_; t += 8) {
        float4 hv = hs4[(size_t)t * 32 + lane];
        float d = fmaf(hv.x, hl.x, fmaf(hv.y, hl.y, fmaf(hv.z, hl.z, hv.w * hl.w)));
        #pragma unroll
        for (int s = 16; s > 0; s >>= 1) d += __shfl_xor_sync(0xffffffffu, d, s);
        if (lane == 0) s_sc[t] = d;
        lmax = fmaxf(lmax, d);
    }
    if (lane == 0) red[warp] = lmax;
    __syncthreads();
    float bmax = red[0];
    #pragma unroll
    for (int w = 1; w < 8; w++) bmax = fmaxf(bmax, red[w]);

    // exp + sum
    float lsum = 0.0f;
    for (int i = tid; i < T_; i += 256) {
        float e = __expf(s_sc[i] - bmax);
        s_sc[i] = e;
        lsum += e;
    }
    red2[tid] = lsum;
    __syncthreads();
    #pragma unroll
    for (int s = 128; s > 0; s >>= 1) {
        if (tid < s) red2[tid] += red2[tid + s];
        __syncthreads();
    }
    const float ssum = red2[0];
    __syncthreads();   // everyone has read red2[0] before reuse

    // weighted sum
    const int j    = tid & 127;
    const int half = tid >> 7;
    float acc = 0.0f;
    for (int t = half; t < T_; t += 2)
        acc = fmaf(s_sc[t], hs[(size_t)t * H_ + j], acc);
    red2[tid] = acc;
    __syncthreads();
    if (tid < 128)
        out[b * H_ + tid] = (red2[tid] + red2[tid + 128]) * __fdividef(1.0f, ssum);
}

// ---------------------------------------------------------------------------
extern "C" void kernel_launch(void* const* d_in, const int* in_sizes, int n_in,
                              void* d_out, int out_size)
{
    (void)in_sizes; (void)n_in; (void)out_size;
    const float* x   = (const float*)d_in[0];
    const float* Wih = (const float*)d_in[1];
    const float* Whh = (const float*)d_in[2];
    const float* bih = (const float*)d_in[3];
    const float* bhh = (const float*)d_in[4];
    float* out = (float*)d_out;

    cudaFuncSetAttribute(xproj_kernel, cudaFuncAttributeMaxDynamicSharedMemorySize, 65536);
    cudaFuncSetAttribute(lstm_kernel,  cudaFuncAttributeMaxDynamicSharedMemorySize, 136192);

    dim3 g1(M_ / 64, G4_ / 64);            // 8192 x 8
    xproj_kernel<<<g1, 256, 65536>>>(x, Wih, bih, bhh);
    lstm_kernel<<<B_ / 2, 256, 136192>>>(Whh);
    attn_kernel<<<B_, 256>>>(out);
}

// round 3
// speedup vs baseline: 2.0368x; 2.0368x over previous
#include <cuda_runtime.h>
#include <cuda_bf16.h>
#include <cstdint>
#include <cstddef>

#define B_  256
#define T_  2048
#define H_  128
#define G4_ 512                 // 4*H
#define M_  (B_ * T_)           // 524288

// Scratch (device globals — no cudaMalloc allowed)
__device__ float g_xp[(size_t)M_ * G4_];   // x @ W_ih^T + b_ih + b_hh   (1 GiB)
__device__ float g_hs[(size_t)M_ * H_];    // h_states [B][T][H]         (256 MiB)

// ===========================================================================
// Helpers
// ===========================================================================
__device__ __forceinline__ uint32_t smem_u32(const void* p) {
    uint32_t a;
    asm("{ .reg .u64 t; cvta.to.shared.u64 t, %1; cvt.u32.u64 %0, t; }"
        : "=r"(a) : "l"(p));
    return a;
}

// Packed fp32x2 FMA (2 fp32 FMAs per issue slot — ptxas never emits from C++)
__device__ __forceinline__ unsigned long long fma2(unsigned long long a,
                                                   unsigned long long b,
                                                   unsigned long long c) {
    unsigned long long d;
    asm("fma.rn.f32x2 %0, %1, %2, %3;" : "=l"(d) : "l"(a), "l"(b), "l"(c));
    return d;
}
__device__ __forceinline__ float sum2(unsigned long long v) {
    float lo, hi;
    asm("mov.b64 {%0, %1}, %2;" : "=f"(lo), "=f"(hi) : "l"(v));
    return lo + hi;
}

__device__ __forceinline__ void ldsm_x4(uint32_t* r, uint32_t addr) {
    asm volatile("ldmatrix.sync.aligned.m8n8.x4.shared.b16 {%0,%1,%2,%3}, [%4];"
                 : "=r"(r[0]), "=r"(r[1]), "=r"(r[2]), "=r"(r[3]) : "r"(addr));
}

__device__ __forceinline__ void mma16816(float* c, const uint32_t* a,
                                         uint32_t b0, uint32_t b1) {
    asm volatile(
        "mma.sync.aligned.m16n8k16.row.col.f32.bf16.bf16.f32 "
        "{%0,%1,%2,%3}, {%4,%5,%6,%7}, {%8,%9}, {%0,%1,%2,%3};"
        : "+f"(c[0]), "+f"(c[1]), "+f"(c[2]), "+f"(c[3])
        : "r"(a[0]), "r"(a[1]), "r"(a[2]), "r"(a[3]), "r"(b0), "r"(b1));
}

// fp32 -> (hi, lo) bf16 pairs packed as u32
__device__ __forceinline__ void split2(float a, float b, uint32_t& hi, uint32_t& lo) {
    __nv_bfloat16 ha = __float2bfloat16_rn(a);
    __nv_bfloat16 hb = __float2bfloat16_rn(b);
    float ra = a - __bfloat162float(ha);
    float rb = b - __bfloat162float(hb);
    __nv_bfloat16 la = __float2bfloat16_rn(ra);
    __nv_bfloat16 lb = __float2bfloat16_rn(rb);
    __nv_bfloat162 hp = __halves2bfloat162(ha, hb);
    __nv_bfloat162 lp = __halves2bfloat162(la, lb);
    hi = *reinterpret_cast<uint32_t*>(&hp);
    lo = *reinterpret_cast<uint32_t*>(&lp);
}

// ===========================================================================
// Kernel 1: x_proj via mma.sync bf16 split-precision GEMM (compute_103-safe).
// CTA: 128 M-rows, loops over N=512 in 8 chunks of 64. K=128 smem-resident.
// Rows are 256B in smem; 16B chunks XOR-swizzled by (row&7) for ldmatrix.
// ===========================================================================
#define XS_AHI  0
#define XS_ALO  32768
#define XS_BHI  65536
#define XS_BLO  81920
#define XS_BIAS 98304
#define XS_SIZE 100352

__global__ __launch_bounds__(256) void xproj_mma_kernel(
    const float* __restrict__ x, const float* __restrict__ Wih,
    const float* __restrict__ bih, const float* __restrict__ bhh)
{
    extern __shared__ __align__(128) char smem[];
    const uint32_t sb = smem_u32(smem);
    const int tid  = threadIdx.x;
    const int wid  = tid >> 5;
    const int lane = tid & 31;
    const int m0   = blockIdx.x * 128;

    float* s_bias = reinterpret_cast<float*>(smem + XS_BIAS);
    if (tid < 256) {
        s_bias[tid]       = bih[tid]       + bhh[tid];
        s_bias[tid + 256] = bih[tid + 256] + bhh[tid + 256];
    }

    // ---- load + split A (x tile: 128 rows x 128 k) ----
    const float4* x4 = reinterpret_cast<const float4*>(x);
    #pragma unroll
    for (int it = 0; it < 16; it++) {
        int idx = tid + it * 256;
        int r   = idx >> 5;
        int k4  = idx & 31;                       // float4 index = 8B of bf16
        float4 v = x4[(size_t)(m0 + r) * 32 + k4];
        uint2 hi, lo;
        split2(v.x, v.y, hi.x, lo.x);
        split2(v.z, v.w, hi.y, lo.y);
        uint32_t ch = (uint32_t)(k4 >> 1) ^ (uint32_t)(r & 7);
        uint32_t off = (uint32_t)r * 256u + ch * 16u + (uint32_t)(k4 & 1) * 8u;
        *reinterpret_cast<uint2*>(smem + XS_AHI + off) = hi;
        *reinterpret_cast<uint2*>(smem + XS_ALO + off) = lo;
    }

    const int wm = wid & 3;         // 4 warps along M (32 rows each)
    const int wn = wid >> 2;        // 2 warps along N (32 cols each)

    // ldmatrix per-thread source rows (fixed across k-steps)
    const int a_row  = wm * 32 + (lane & 15);            // + mi*16
    const int a_koff = lane >> 4;                        // 0/1 -> k halves
    const int b_row  = ((lane >> 4) << 3) + (lane & 7);  // n row within 16-block
    const int b_koff = (lane >> 3) & 1;

    const float4* w4 = reinterpret_cast<const float4*>(Wih);

    for (int nc = 0; nc < 8; nc++) {
        const int n0g = nc * 64;

        // ---- load + split B (W chunk: 64 rows x 128 k) ----
        #pragma unroll
        for (int it = 0; it < 8; it++) {
            int idx = tid + it * 256;
            int r   = idx >> 5;
            int k4  = idx & 31;
            float4 v = w4[(size_t)(n0g + r) * 32 + k4];
            uint2 hi, lo;
            split2(v.x, v.y, hi.x, lo.x);
            split2(v.z, v.w, hi.y, lo.y);
            uint32_t ch = (uint32_t)(k4 >> 1) ^ (uint32_t)(r & 7);
            uint32_t off = (uint32_t)r * 256u + ch * 16u + (uint32_t)(k4 & 1) * 8u;
            *reinterpret_cast<uint2*>(smem + XS_BHI + off) = hi;
            *reinterpret_cast<uint2*>(smem + XS_BLO + off) = lo;
        }
        __syncthreads();

        float acc[2][4][4];
        #pragma unroll
        for (int mi = 0; mi < 2; mi++)
            #pragma unroll
            for (int ni = 0; ni < 4; ni++)
                #pragma unroll
                for (int q = 0; q < 4; q++) acc[mi][ni][q] = 0.0f;

        #pragma unroll
        for (int ks = 0; ks < 8; ks++) {
            uint32_t ahi[2][4], alo[2][4];
            #pragma unroll
            for (int mi = 0; mi < 2; mi++) {
                int r = a_row + mi * 16;
                uint32_t ch = (uint32_t)(ks * 2 + a_koff) ^ (uint32_t)(r & 7);
                uint32_t ad = sb + (uint32_t)r * 256u + ch * 16u;
                ldsm_x4(ahi[mi], ad + XS_AHI);
                ldsm_x4(alo[mi], ad + XS_ALO);
            }
            uint32_t bhi[2][4], blo[2][4];
            #pragma unroll
            for (int p = 0; p < 2; p++) {       // two n16 blocks -> 4 n8 tiles
                int r = wn * 32 + p * 16 + b_row;
                uint32_t ch = (uint32_t)(ks * 2 + b_koff) ^ (uint32_t)(r & 7);
                uint32_t ad = sb + (uint32_t)r * 256u + ch * 16u;
                ldsm_x4(bhi[p], ad + XS_BHI);
                ldsm_x4(blo[p], ad + XS_BLO);
            }
            #pragma unroll
            for (int mi = 0; mi < 2; mi++)
                #pragma unroll
                for (int ni = 0; ni < 4; ni++) {
                    int p = ni >> 1, q = ni & 1;
                    mma16816(acc[mi][ni], ahi[mi], bhi[p][q * 2], bhi[p][q * 2 + 1]);
                    mma16816(acc[mi][ni], ahi[mi], blo[p][q * 2], blo[p][q * 2 + 1]);
                    mma16816(acc[mi][ni], alo[mi], bhi[p][q * 2], bhi[p][q * 2 + 1]);
                }
        }

        // ---- epilogue: add bias, store fp32 to g_xp ----
        #pragma unroll
        for (int mi = 0; mi < 2; mi++) {
            #pragma unroll
            for (int ni = 0; ni < 4; ni++) {
                int ncol = n0g + wn * 32 + ni * 8 + (lane & 3) * 2;
                int mrow = m0 + wm * 32 + mi * 16 + (lane >> 2);
                float bx = s_bias[ncol], by = s_bias[ncol + 1];
                float2 v0 = make_float2(acc[mi][ni][0] + bx, acc[mi][ni][1] + by);
                float2 v1 = make_float2(acc[mi][ni][2] + bx, acc[mi][ni][3] + by);
                *reinterpret_cast<float2*>(g_xp + (size_t)mrow * G4_ + ncol) = v0;
                *reinterpret_cast<float2*>(g_xp + (size_t)(mrow + 8) * G4_ + ncol) = v1;
            }
        }
        __syncthreads();   // protect B smem before next chunk's reload
    }
}

// ===========================================================================
// Kernel 2: persistent LSTM scan, f32x2-packed FMAs (packing along k).
// 128 CTAs x 2 batch rows x 256 threads.
// Gate rows 0..255 in registers (u64 k-pairs), rows 256..511 streamed from smem.
// ===========================================================================
__device__ __forceinline__ float sigmoid_f(float v) {
    return __fdividef(1.0f, 1.0f + __expf(-v));
}
__device__ __forceinline__ float tanh_f(float v) {
    return 1.0f - __fdividef(2.0f, __expf(2.0f * v) + 1.0f);
}

__global__ __launch_bounds__(256, 1) void lstm_kernel(const float* __restrict__ Whh)
{
    extern __shared__ float smem_l[];
    float*  sh_h = smem_l;                 // [2][128]
    float*  gbuf = smem_l + 256;           // [2][512]
    float4* Wgo  = reinterpret_cast<float4*>(smem_l + 256 + 1024); // [32][256] float4

    const int tid = threadIdx.x;
    const int b0  = blockIdx.x * 2;

    // Register-resident W row `tid` as 64 packed u64 (k-pairs)
    unsigned long long wr[64];
    {
        const ulonglong2* Wll = reinterpret_cast<const ulonglong2*>(Whh);
        #pragma unroll
        for (int i = 0; i < 32; i++) {
            ulonglong2 v = Wll[(size_t)tid * 32 + i];
            wr[2 * i]     = v.x;
            wr[2 * i + 1] = v.y;
        }
    }
    // smem-resident W rows 256..511, transposed to [k4][row]
    #pragma unroll
    for (int i = 0; i < 32; i++) {
        int idx = tid + 256 * i;
        int k4  = idx >> 8;
        int r   = idx & 255;
        Wgo[k4 * 256 + r] = reinterpret_cast<const float4*>(Whh)[(size_t)(256 + r) * 32 + k4];
    }

    sh_h[tid] = 0.0f;
    float c_reg = 0.0f;

    const int row = tid >> 7;
    const int j   = tid & 127;
    const float* my_xp = g_xp + (size_t)(b0 + row) * T_ * G4_;
    float*       my_hs = g_hs + (size_t)(b0 + row) * T_ * H_;

    __syncthreads();

    for (int t = 0; t < T_; t++) {
        const float* xpt = my_xp + (size_t)t * G4_;
        float xpi = __ldg(xpt + j);
        float xpf = __ldg(xpt + 128 + j);
        float xpg = __ldg(xpt + 256 + j);
        float xpo = __ldg(xpt + 384 + j);

        // -------- phase A: packed dot products --------
        unsigned long long aa0 = 0ull, aa1 = 0ull, qq0 = 0ull, qq1 = 0ull;
        #pragma unroll
        for (int k4 = 0; k4 < 32; k4++) {
            ulonglong2 h0 = *reinterpret_cast<const ulonglong2*>(sh_h + k4 * 4);        // bcast
            ulonglong2 h1 = *reinterpret_cast<const ulonglong2*>(sh_h + 128 + k4 * 4);  // bcast
            ulonglong2 wg = *reinterpret_cast<const ulonglong2*>(&Wgo[k4 * 256 + tid]); // stream
            aa0 = fma2(wr[2 * k4], h0.x, aa0); aa0 = fma2(wr[2 * k4 + 1], h0.y, aa0);
            aa1 = fma2(wr[2 * k4], h1.x, aa1); aa1 = fma2(wr[2 * k4 + 1], h1.y, aa1);
            qq0 = fma2(wg.x, h0.x, qq0);       qq0 = fma2(wg.y, h0.y, qq0);
            qq1 = fma2(wg.x, h1.x, qq1);       qq1 = fma2(wg.y, h1.y, qq1);
        }
        gbuf[tid]       = sum2(aa0);   // gate-row tid,     batch row 0
        gbuf[512 + tid] = sum2(aa1);   // gate-row tid,     batch row 1
        gbuf[256 + tid] = sum2(qq0);   // gate-row 256+tid, batch row 0
        gbuf[768 + tid] = sum2(qq1);   // gate-row 256+tid, batch row 1
        __syncthreads();

        // -------- phase B: LSTM cell update --------
        float gi = gbuf[row * 512 + j]       + xpi;
        float gf = gbuf[row * 512 + 128 + j] + xpf;
        float gg = gbuf[row * 512 + 256 + j] + xpg;
        float go = gbuf[row * 512 + 384 + j] + xpo;

        float si = sigmoid_f(gi);
        float sf = sigmoid_f(gf);
        float so = sigmoid_f(go);
        float tg = tanh_f(gg);

        c_reg = fmaf(sf, c_reg, si * tg);
        float hn = so * tanh_f(c_reg);

        sh_h[row * 128 + j]       = hn;
        my_hs[(size_t)t * H_ + j] = hn;
        __syncthreads();
    }
}

// ===========================================================================
// Kernel 3: attention pooling. One CTA per batch row.
// ===========================================================================
__global__ __launch_bounds__(256) void attn_kernel(float* __restrict__ out)
{
    __shared__ float s_sc[T_];
    __shared__ float red[8];
    __shared__ float red2[256];

    const int b    = blockIdx.x;
    const int tid  = threadIdx.x;
    const int lane = tid & 31;
    const int warp = tid >> 5;

    const float*  hs  = g_hs + (size_t)b * T_ * H_;
    const float4* hs4 = reinterpret_cast<const float4*>(hs);

    const float4 hl = hs4[(size_t)(T_ - 1) * 32 + lane];

    float lmax = -3.0e38f;
    for (int t = warp; t < T_; t += 8) {
        float4 hv = hs4[(size_t)t * 32 + lane];
        float d = fmaf(hv.x, hl.x, fmaf(hv.y, hl.y, fmaf(hv.z, hl.z, hv.w * hl.w)));
        #pragma unroll
        for (int s = 16; s > 0; s >>= 1) d += __shfl_xor_sync(0xffffffffu, d, s);
        if (lane == 0) s_sc[t] = d;
        lmax = fmaxf(lmax, d);
    }
    if (lane == 0) red[warp] = lmax;
    __syncthreads();
    float bmax = red[0];
    #pragma unroll
    for (int w = 1; w < 8; w++) bmax = fmaxf(bmax, red[w]);

    float lsum = 0.0f;
    for (int i = tid; i < T_; i += 256) {
        float e = __expf(s_sc[i] - bmax);
        s_sc[i] = e;
        lsum += e;
    }
    red2[tid] = lsum;
    __syncthreads();
    #pragma unroll
    for (int s = 128; s > 0; s >>= 1) {
        if (tid < s) red2[tid] += red2[tid + s];
        __syncthreads();
    }
    const float ssum = red2[0];
    __syncthreads();

    const int j    = tid & 127;
    const int half = tid >> 7;
    float acc = 0.0f;
    for (int t = half; t < T_; t += 2)
        acc = fmaf(s_sc[t], hs[(size_t)t * H_ + j], acc);
    red2[tid] = acc;
    __syncthreads();
    if (tid < 128)
        out[b * H_ + tid] = (red2[tid] + red2[tid + 128]) * __fdividef(1.0f, ssum);
}

// ===========================================================================
extern "C" void kernel_launch(void* const* d_in, const int* in_sizes, int n_in,
                              void* d_out, int out_size)
{
    (void)in_sizes; (void)n_in; (void)out_size;
    const float* x   = (const float*)d_in[0];
    const float* Wih = (const float*)d_in[1];
    const float* Whh = (const float*)d_in[2];
    const float* bih = (const float*)d_in[3];
    const float* bhh = (const float*)d_in[4];
    float* out = (float*)d_out;

    cudaFuncSetAttribute(xproj_mma_kernel, cudaFuncAttributeMaxDynamicSharedMemorySize, XS_SIZE);
    cudaFuncSetAttribute(lstm_kernel,      cudaFuncAttributeMaxDynamicSharedMemorySize, 136192);

    xproj_mma_kernel<<<M_ / 128, 256, XS_SIZE>>>(x, Wih, bih, bhh);
    lstm_kernel<<<B_ / 2, 256, 136192>>>(Whh);
    attn_kernel<<<B_, 256>>>(out);
}